// round 17
// baseline (speedup 1.0000x reference)
#include <cuda_runtime.h>
#include <cuda_fp16.h>

typedef unsigned long long ull;

#define Bb 256
#define Tt 512
#define Vv 30000
#define Ee 256

// ---------------- static device scratch ----------------
__device__ __half g_embedW[(size_t)Vv * 192];      // [V][192] fwd 0..95, bwd 96..191 (bih folded, r/z pre-halved), fp16
__device__ float  g_x1[(size_t)Bb * Tt * 64];      // layer0 outputs [B][T][64], fp32
__device__ __half g_gi1[(size_t)Bb * Tt * 192];    // layer1 input gates (r/z pre-halved), fp16

// ---------------- fast math ----------------
__device__ __forceinline__ float fast_tanh(float x) {
    float y; asm("tanh.approx.f32 %0, %1;" : "=f"(y) : "f"(x));
    return y;
}
__device__ __forceinline__ void fma2(ull& d, ull a, ull b) {
    asm("fma.rn.f32x2 %0, %1, %2, %0;" : "+l"(d) : "l"(a), "l"(b));
}
__device__ __forceinline__ ull add2(ull a, ull b) {
    ull r; asm("add.rn.f32x2 %0, %1, %2;" : "=l"(r) : "l"(a), "l"(b));
    return r;
}
__device__ __forceinline__ ull dup2(float v) {
    ull r; asm("mov.b64 %0, {%1, %1};" : "=l"(r) : "f"(v));
    return r;
}
__device__ __forceinline__ ull pack2(float lo, float hi) {
    ull r; asm("mov.b64 %0, {%1, %2};" : "=l"(r) : "f"(lo), "f"(hi));
    return r;
}
__device__ __forceinline__ float hsum2(ull v) {
    unsigned lo, hi;
    asm("mov.b64 {%0, %1}, %2;" : "=r"(lo), "=r"(hi) : "l"(v));
    return __uint_as_float(lo) + __uint_as_float(hi);
}

// ---------------- fused GEMM: C[M,192] = half((A[M,K] @ [Wf;Wb]^T + bias) * colscale) ----------------
// BM=64, BN=192, BK=16, 256 threads, single-buffer smem, 3 CTAs/SM.  (R6 proven config; fp16 output)
__global__ __launch_bounds__(256, 3)
void gemm192_kernel(const float* __restrict__ A,
                    const float* __restrict__ Wf, const float* __restrict__ Wb,
                    const float* __restrict__ bf, const float* __restrict__ bb_,
                    __half* __restrict__ C, int M, int K,
                    const int* __restrict__ rowmask)
{
    __shared__ float As[16][68];
    __shared__ float Bs[16][196];

    int m0 = blockIdx.x * 64;
    if (rowmask && rowmask[m0] == 0) return;   // prefix mask: whole 64-row block padded

    int tid = threadIdx.x;
    int tx = tid & 31;        // cols tx + 32*j, j=0..5
    int ty = tid >> 5;        // rows ty*8 .. ty*8+7
    int lkk = tid & 15;
    int lrow = tid >> 4;

    const float* abase = A + (m0 + lrow) * K + lkk;
    const float* wfb = Wf + lrow * K + lkk;
    const float* wbb = Wb + lrow * K + lkk;
    bool arow_ok[4];
#pragma unroll
    for (int p = 0; p < 4; p++) arow_ok[p] = (m0 + lrow + 16 * p) < M;
    int K16 = K * 16;

    ull acc[4][6];
#pragma unroll
    for (int i = 0; i < 4; i++)
#pragma unroll
        for (int j = 0; j < 6; j++) acc[i][j] = 0ull;

    for (int k0 = 0; k0 < K; k0 += 16) {
#pragma unroll
        for (int p = 0; p < 4; p++)
            As[lkk][lrow + 16 * p] = arow_ok[p] ? abase[p * K16 + k0] : 0.f;
#pragma unroll
        for (int p = 0; p < 6; p++)
            Bs[lkk][lrow + 16 * p] = wfb[p * K16 + k0];
#pragma unroll
        for (int p = 6; p < 12; p++)
            Bs[lkk][lrow + 16 * p] = wbb[(p - 6) * K16 + k0];
        __syncthreads();
#pragma unroll
        for (int k = 0; k < 16; k++) {
            ulonglong2 q0 = *(const ulonglong2*)&As[k][ty * 8];
            ulonglong2 q1 = *(const ulonglong2*)&As[k][ty * 8 + 4];
            ull a2[4] = { q0.x, q0.y, q1.x, q1.y };
            ull b2[6];
#pragma unroll
            for (int j = 0; j < 6; j++) b2[j] = dup2(Bs[k][tx + 32 * j]);
#pragma unroll
            for (int i = 0; i < 4; i++)
#pragma unroll
                for (int j = 0; j < 6; j++)
                    fma2(acc[i][j], a2[i], b2[j]);
        }
        __syncthreads();
    }

#pragma unroll
    for (int j = 0; j < 6; j++) {
        int n = tx + 32 * j;
        // j: 0=r_f 1=z_f 2=n_f 3=r_b 4=z_b 5=n_b ; r/z pre-halved for tanh-form sigmoid
        float scale = (j == 2 || j == 5) ? 1.0f : 0.5f;
        float bias = (j < 3) ? bf[n] : bb_[n - 96];
#pragma unroll
        for (int i = 0; i < 4; i++) {
            int gm0 = m0 + ty * 8 + 2 * i;
            unsigned lo, hi;
            asm("mov.b64 {%0, %1}, %2;" : "=r"(lo), "=r"(hi) : "l"(acc[i][j]));
            if (gm0 < M)     C[(size_t)gm0 * 192 + n]       = __float2half_rn((__uint_as_float(lo) + bias) * scale);
            if (gm0 + 1 < M) C[(size_t)(gm0 + 1) * 192 + n] = __float2half_rn((__uint_as_float(hi) + bias) * scale);
        }
    }
}

// ---------------- GRU recurrence: warp = (batch, dir)  (R13 core; fp16 gi stream) ----------------
template<bool L0>
__global__ __launch_bounds__(128)
void gru_kernel(const __half* __restrict__ gi,
                const int* __restrict__ ids,
                const int* __restrict__ mask,
                const float* __restrict__ Whh_f, const float* __restrict__ bhh_f,
                const float* __restrict__ Whh_b, const float* __restrict__ bhh_b,
                const float* __restrict__ Wout, const float* __restrict__ bout,
                float* __restrict__ out)
{
    __shared__ float sh[4][2][32];        // [warp][parity][lane]
    __shared__ int   sid[4][Tt];          // L0 only
    __shared__ float stop[2][64];         // L1 only: [pair-in-CTA][dir*32+lane]

    int wib = threadIdx.x >> 5;
    int lane = threadIdx.x & 31;
    int w = blockIdx.x * 4 + wib;
    int dir = w & 1;
    int b   = w >> 1;
    const float* Whh = dir ? Whh_b : Whh_f;
    const float* bhh = dir ? bhh_b : bhh_f;

    // Whh rows packed as f32x2 pairs; r/z rows pre-halved (tanh-form sigmoid)
    ull Wr2[16], Wz2[16], Wn2[16];
#pragma unroll
    for (int q = 0; q < 8; q++) {
        float4 v;
        v = *(const float4*)&Whh[lane * 32 + q * 4];
        Wr2[2*q]   = pack2(0.5f * v.x, 0.5f * v.y);
        Wr2[2*q+1] = pack2(0.5f * v.z, 0.5f * v.w);
        v = *(const float4*)&Whh[(32 + lane) * 32 + q * 4];
        Wz2[2*q]   = pack2(0.5f * v.x, 0.5f * v.y);
        Wz2[2*q+1] = pack2(0.5f * v.z, 0.5f * v.w);
        v = *(const float4*)&Whh[(64 + lane) * 32 + q * 4];
        Wn2[2*q]   = pack2(v.x, v.y);
        Wn2[2*q+1] = pack2(v.z, v.w);
    }
    ull bR = pack2(0.5f * bhh[lane], 0.f);
    ull bZ = pack2(0.5f * bhh[32 + lane], 0.f);
    ull bN = pack2(bhh[64 + lane], 0.f);

    // per-warp length from prefix mask (fused lens)
    int len = 0;
    {
        const int* mrow = mask + b * Tt;
#pragma unroll
        for (int i = 0; i < Tt / 32; i++) len += mrow[lane + 32 * i];
#pragma unroll
        for (int off = 16; off; off >>= 1) len += __shfl_xor_sync(0xffffffffu, len, off);
    }
    int lenm1 = len - 1;

    if (L0) {
        const int* idrow = ids + b * Tt;
        for (int i = lane; i < len; i += 32) sid[wib][i] = idrow[i];
        __syncwarp();
    }

    int tstep = dir ? -1 : 1;
    int tcur  = dir ? lenm1 : 0;

    // direction-adjusted base pointers
    const __half* gi0  = gi + dir * 96;                              // L0: + sid[t]*192
    const __half* gib  = gi + (size_t)b * Tt * 192 + dir * 96;       // L1: + t*192

    // clamped time index, branch-free
    auto tclamp = [&](int t) { return min(max(t, 0), lenm1); };
    auto gip = [&](int t) -> const __half* {
        if (L0) return gi0 + (size_t)sid[wib][t] * 192;
        else    return gib + (size_t)t * 192;
    };

    // distance-3 prefetch pipeline (clamped -> no init branches)
    const __half* p;
    p = gip(tclamp(tcur));
    float p0r = __half2float(__ldg(p + lane)), p0z = __half2float(__ldg(p + 32 + lane)), p0n = __half2float(__ldg(p + 64 + lane));
    p = gip(tclamp(tcur + tstep));
    float p1r = __half2float(__ldg(p + lane)), p1z = __half2float(__ldg(p + 32 + lane)), p1n = __half2float(__ldg(p + 64 + lane));
    p = gip(tclamp(tcur + 2 * tstep));
    float p2r = __half2float(__ldg(p + lane)), p2z = __half2float(__ldg(p + 32 + lane)), p2n = __half2float(__ldg(p + 64 + lane));

    float h = 0.f;
    float* outp = L0 ? (g_x1 + ((size_t)b * Tt + tcur) * 64 + dir * 32 + lane) : nullptr;
    int outstep = tstep * 64;

#pragma unroll 6
    for (int s = 0; s < len; s++) {
        float cr = p0r, cz = p0z, cn = p0n;
        p0r = p1r; p0z = p1z; p0n = p1n;
        p1r = p2r; p1z = p2z; p1n = p2n;
        // branch-free clamped prefetch (redundant tail loads are harmless)
        p = gip(tclamp(tcur + 3 * tstep));
        p2r = __half2float(__ldg(p + lane));
        p2z = __half2float(__ldg(p + 32 + lane));
        p2n = __half2float(__ldg(p + 64 + lane));

        if (!L0) {
            // backstop: stage step t+8's lines into L2
            const __half* pf = gib + (size_t)tclamp(tcur + 8 * tstep) * 192;
            asm volatile("prefetch.global.L2 [%0];" :: "l"(pf + lane));
            asm volatile("prefetch.global.L2 [%0];" :: "l"(pf + 32 + lane));
            asm volatile("prefetch.global.L2 [%0];" :: "l"(pf + 64 + lane));
        }

        int par = s & 1;
        sh[wib][par][lane] = h;
        __syncwarp();
        ull h2[16];
#pragma unroll
        for (int i = 0; i < 8; i++) {
            ulonglong2 q2 = *(const ulonglong2*)&sh[wib][par][4 * i];
            h2[2 * i] = q2.x; h2[2 * i + 1] = q2.y;
        }

        ull ra = bR, rb = 0ull, za = bZ, zb = 0ull, na = bN, nb2 = 0ull;
#pragma unroll
        for (int k = 0; k < 16; k += 2) {
            fma2(na,  Wn2[k],     h2[k]);
            fma2(nb2, Wn2[k + 1], h2[k + 1]);
            fma2(ra,  Wr2[k],     h2[k]);
            fma2(rb,  Wr2[k + 1], h2[k + 1]);
            fma2(za,  Wz2[k],     h2[k]);
            fma2(zb,  Wz2[k + 1], h2[k + 1]);
        }
        float ar = hsum2(add2(ra, rb));
        float az = hsum2(add2(za, zb));
        float an = hsum2(add2(na, nb2));

        // sigmoid(x) = 0.5 + 0.5*tanh(x/2); r/z args pre-halved upstream
        float r = fmaf(0.5f, fast_tanh(cr + ar), 0.5f);
        float z = fmaf(0.5f, fast_tanh(cz + az), 0.5f);
        float n = fast_tanh(fmaf(r, an, cn));
        h = fmaf(z, h - n, n);

        if (L0) { *outp = h; outp += outstep; }
        tcur += tstep;
    }

    if (!L0) {
        // fused output projection: warps (b,fwd) and (b,bwd) are CTA-adjacent
        int pi = wib >> 1;                       // batch pair index within CTA
        stop[pi][dir * 32 + lane] = h;
        __syncthreads();
        if (dir == 0) {
            float t0 = stop[pi][lane];
            float t1 = stop[pi][32 + lane];
#pragma unroll
            for (int o = 0; o < 6; o++) {
                float s2 = t0 * Wout[o * 64 + lane] + t1 * Wout[o * 64 + 32 + lane];
#pragma unroll
                for (int off = 16; off; off >>= 1) s2 += __shfl_xor_sync(0xffffffffu, s2, off);
                if (lane == 0) out[b * 6 + o] = s2 + bout[o];
            }
        }
    }
}

// ---------------- launch ----------------
extern "C" void kernel_launch(void* const* d_in, const int* in_sizes, int n_in,
                              void* d_out, int out_size)
{
    const int*   ids     = (const int*)d_in[0];
    const int*   mask    = (const int*)d_in[1];
    const float* embed   = (const float*)d_in[2];
    const float* Wih_l0f = (const float*)d_in[3];
    const float* Whh_l0f = (const float*)d_in[4];
    const float* bih_l0f = (const float*)d_in[5];
    const float* bhh_l0f = (const float*)d_in[6];
    const float* Wih_l0b = (const float*)d_in[7];
    const float* Whh_l0b = (const float*)d_in[8];
    const float* bih_l0b = (const float*)d_in[9];
    const float* bhh_l0b = (const float*)d_in[10];
    const float* Wih_l1f = (const float*)d_in[11];
    const float* Whh_l1f = (const float*)d_in[12];
    const float* bih_l1f = (const float*)d_in[13];
    const float* bhh_l1f = (const float*)d_in[14];
    const float* Wih_l1b = (const float*)d_in[15];
    const float* Whh_l1b = (const float*)d_in[16];
    const float* bih_l1b = (const float*)d_in[17];
    const float* bhh_l1b = (const float*)d_in[18];
    const float* Wout    = (const float*)d_in[19];
    const float* bout    = (const float*)d_in[20];
    float* out = (float*)d_out;

    __half *p_embedW = nullptr, *p_gi1 = nullptr;
    float  *p_x1 = nullptr;
    cudaGetSymbolAddress((void**)&p_embedW, g_embedW);
    cudaGetSymbolAddress((void**)&p_x1, g_x1);
    cudaGetSymbolAddress((void**)&p_gi1, g_gi1);

    // 1) embedW = half((embed @ [Wih_l0f;Wih_l0b]^T + bias) * colscale)   — 11.5 MB, L2-resident
    gemm192_kernel<<<(Vv + 63) / 64, 256>>>(embed, Wih_l0f, Wih_l0b, bih_l0f, bih_l0b,
                                            p_embedW, Vv, Ee, nullptr);
    // 2) layer-0 bidirectional recurrence -> x1 (fp32)
    gru_kernel<true><<<128, 128>>>(p_embedW, ids, mask, Whh_l0f, bhh_l0f, Whh_l0b, bhh_l0b,
                                   nullptr, nullptr, nullptr);
    // 3) gi1 = half((x1 @ [Wih_l1f;Wih_l1b]^T + bias) * colscale)  — 24.5 MB masked, L2-resident
    gemm192_kernel<<<(Bb * Tt) / 64, 256>>>(p_x1, Wih_l1f, Wih_l1b, bih_l1f, bih_l1b,
                                            p_gi1, Bb * Tt, 64, mask);
    // 4) layer-1 recurrence + fused output projection (+ gi1 L2 prefetch backstop)
    gru_kernel<false><<<128, 128>>>(p_gi1, nullptr, mask, Whh_l1f, bhh_l1f, Whh_l1b, bhh_l1b,
                                    Wout, bout, out);
}